// round 16
// baseline (speedup 1.0000x reference)
#include <cuda_runtime.h>
#include <cuda_bf16.h>
#include <cstdint>

// Problem constants (fixed shapes from the reference)
#define N_NODES   100000
#define NFEATS    256
#define HIDDEN    128
#define NCLASS    64
#define BATCH     1024
#define K0        25
#define K1        10
#define NHIST     5
#define ROWS_TOTAL (BATCH + BATCH * K1)   // 11264 layer0 rows
#define GROWBLK    (ROWS_TOTAL / 2)        // 5632 row blocks (2 rows each)
#define WBLK       8                       // W0-transpose blocks (FIRST in grid)
#define MTILE      128                     // GEMM M tile
#define MT_TOTAL   (ROWS_TOTAL / MTILE)    // 88 m-tiles
#define KDIM       (2 * NFEATS)            // 512
#define KCH        64                      // k-chunk (32 KB of A)
#define NCHUNKS    (KDIM / KCH)            // 8
#define FB         4                       // roots per block in final kernel
#define FNBLK      (BATCH / FB)            // 256 blocks
// GEMM smem map: B-half 128K | A 2 x 32K chunks | bias
#define SA_OFF     131072
#define B0_OFF     (SA_OFF + 2 * 32768)    // 196608
#define GEMM_SMEM  (B0_OFF + 512)          // 197120

// ---------------- device scratch ----------------
__device__ __align__(16) float g_L0[(size_t)ROWS_TOTAL * HIDDEN];
__device__ __align__(16) float g_A[(size_t)ROWS_TOTAL * KDIM];   // tf32-rounded x
__device__ __align__(16) float g_B[(size_t)HIDDEN * KDIM];       // tf32 W0^T [n][k]
// PDL handshake counters (zero-init at load; reset by final_kernel each call)
__device__ int g_tile_cnt[MT_TOTAL];      // 64 row-block arrivals per 128-row tile
__device__ int g_bcnt;                    // 8 W0-transpose arrivals

#define SMEM_SWIZZLE_128B(o) ((o) ^ (((o) >> 3) & 0x70))

__device__ __forceinline__ uint32_t smem_to_u32(const void* p) {
    uint32_t a;
    asm("{ .reg .u64 t; cvta.to.shared.u64 t, %1; cvt.u32.u64 %0, t; }" : "=r"(a) : "l"(p));
    return a;
}
__device__ __forceinline__ float tf32_rna(float x) {
    uint32_t r;
    asm("cvt.rna.tf32.f32 %0, %1;" : "=r"(r) : "f"(x));
    return __uint_as_float(r);
}
__device__ __forceinline__ int ld_acquire(const int* p) {
    int v;
    asm volatile("ld.acquire.gpu.b32 %0, [%1];" : "=r"(v) : "l"(p) : "memory");
    return v;
}
__device__ __forceinline__ void cp_async16(uint32_t dst, const void* src) {
    asm volatile("cp.async.cg.shared.global [%0], [%1], 16;" :: "r"(dst), "l"(src));
}
#define CP_COMMIT()  asm volatile("cp.async.commit_group;" ::: "memory")
#define CP_WAIT(n)   asm volatile("cp.async.wait_group %0;" :: "n"(n) : "memory")

__device__ __forceinline__ void ldsm_x4(uint32_t addr, uint32_t& r0, uint32_t& r1,
                                        uint32_t& r2, uint32_t& r3) {
    asm volatile("ldmatrix.sync.aligned.m8n8.x4.shared.b16 {%0,%1,%2,%3}, [%4];"
                 : "=r"(r0), "=r"(r1), "=r"(r2), "=r"(r3) : "r"(addr));
}
__device__ __forceinline__ void mma_tf32(float* d, uint32_t a0, uint32_t a1,
                                         uint32_t a2, uint32_t a3,
                                         uint32_t b0, uint32_t b1) {
    asm volatile(
        "mma.sync.aligned.m16n8k8.row.col.f32.tf32.tf32.f32 "
        "{%0,%1,%2,%3}, {%4,%5,%6,%7}, {%8,%9}, {%0,%1,%2,%3};"
        : "+f"(d[0]), "+f"(d[1]), "+f"(d[2]), "+f"(d[3])
        : "r"(a0), "r"(a1), "r"(a2), "r"(a3), "r"(b0), "r"(b1));
}

// ============================================================================
// Kernel 1 (PDL primary): gather + mean -> tf32 fp32 scratch.
// Blocks [0,8): W0 transpose (FIRST so g_B completes early); signal g_bcnt.
// Blocks [8,5640): 2 rows each; signal g_tile_cnt[tile] (64 per 128-row tile).
// Every block fires griddepcontrol.launch_dependents at entry so the gemm
// (secondary) launches as soon as all gather blocks are scheduled.
// ============================================================================
__global__ __launch_bounds__(128)
void gather_kernel(const float* __restrict__ feats,
                   const float* __restrict__ W0,
                   const int*   __restrict__ nodes,
                   const int*   __restrict__ neighs0,
                   const int*   __restrict__ neighs1,
                   const int*   __restrict__ neighs0_nb)
{
    asm volatile("griddepcontrol.launch_dependents;");
    const int t = threadIdx.x;

    if (blockIdx.x < WBLK) {            // ---- W0 transpose (tf32), full 64K ----
        const int b = blockIdx.x;
        #pragma unroll 4
        for (int j = 0; j < 64; j++) {
            const int idx = b * 8192 + j * 128 + t;   // idx = k*128 + n
            const int k = idx >> 7, n = idx & 127;
            g_B[(size_t)n * KDIM + k] = tf32_rna(W0[idx]);
        }
        __syncthreads();
        if (t == 0) { __threadfence(); atomicAdd(&g_bcnt, 1); }
        return;
    }

    const int rb   = blockIdx.x - WBLK; // row-block 0..5631
    const int half = t >> 6;
    const int tc   = t & 63;
    const int row  = rb * 2 + half;
    const float4* f4 = (const float4*)feats;

    int self;
    const int* nb;
    if (row < BATCH) {
        self = nodes[row];
        nb   = neighs0 + row * K0;
    } else {
        const int j = row - BATCH;
        self = neighs1[j];
        nb   = neighs0_nb + j * K0;
    }
    const float4 sv = f4[(size_t)self * (NFEATS / 4) + tc];
    float s0 = 0.f, s1 = 0.f, s2 = 0.f, s3 = 0.f;
    #pragma unroll
    for (int k = 0; k < K0; k++) {
        const float4 v = f4[(size_t)nb[k] * (NFEATS / 4) + tc];
        s0 += v.x; s1 += v.y; s2 += v.z; s3 += v.w;
    }
    const float inv = 1.f / K0;

    float4* A4 = (float4*)(g_A + (size_t)row * KDIM);
    A4[tc] = make_float4(tf32_rna(sv.x), tf32_rna(sv.y),
                         tf32_rna(sv.z), tf32_rna(sv.w));
    A4[64 + tc] = make_float4(tf32_rna(s0 * inv), tf32_rna(s1 * inv),
                              tf32_rna(s2 * inv), tf32_rna(s3 * inv));

    __syncthreads();                    // both rows of this block stored
    if (t == 0) {
        __threadfence();                // publish before signaling
        atomicAdd(&g_tile_cnt[rb >> 6], 1);
    }
}

// ============================================================================
// Kernel 2 (PDL secondary): TF32 GEMM, 32x32 warp tiles (R14-validated body).
// grid 176 x 256 thr. bid: nh = bid&1 (N-half), mt = bid>>1.
// Spins (acquire + nanosleep) on g_bcnt==8 before staging B, and on
// g_tile_cnt[mt]==64 before streaming A -> safe to run concurrently with
// gather under PDL. Falls back to plain serial launch if PDL is rejected.
// ============================================================================
__global__ __launch_bounds__(256)
void gemm_kernel(const float* __restrict__ b0)
{
    extern __shared__ __align__(1024) char sm[];
    float* b0s = (float*)(sm + B0_OFF);
    const uint32_t smb = smem_to_u32(sm);
    const int tid  = threadIdx.x;
    const int lane = tid & 31;
    const int w    = tid >> 5;
    const int wm   = (w & 3) * 32;      // 4 m-strips of 32 rows
    const int wn   = (w >> 2) * 32;     // 2 n-strips of 32 cols (within half)
    const int nh   = blockIdx.x & 1;
    const int mt   = blockIdx.x >> 1;   // 0..87

    for (int i = tid; i < HIDDEN; i += 256) b0s[i] = b0[i];

    // ---- wait for W0 transpose, then stage B-half (16 k-planes x 8 KB) ----
    if (tid == 0) {
        while (ld_acquire(&g_bcnt) != WBLK) __nanosleep(64);
        __threadfence();
    }
    __syncthreads();
    {
        const char* Bh = (const char*)(g_B + (size_t)(nh * 64) * KDIM);
        #pragma unroll
        for (int q = 0; q < 32; q++) {
            const int id = tid + 256 * q;        // 0..8191
            const int r = id >> 7, c = id & 127; // n-row, 16B-unit
            const uint32_t doff = (c >> 3) * 8192
                                + SMEM_SWIZZLE_128B(r * 128 + (c & 7) * 16);
            cp_async16(smb + doff, Bh + (size_t)r * 2048 + c * 16);
        }
        CP_COMMIT();                             // group: B
    }

    // ---- wait for this block's A tile to be fully gathered ----
    if (tid == 0) {
        while (ld_acquire(&g_tile_cnt[mt]) != 64) __nanosleep(64);
        __threadfence();
    }
    __syncthreads();

    const size_t arow0 = (size_t)mt * MTILE;
    const char* Ag = (const char*)(g_A + arow0 * KDIM);

    // A chunk copy: [128 rows][64 k] = 2048 x 16B units, 8 per thread
    auto copyA = [&](int ch, int buf) {
        #pragma unroll
        for (int q = 0; q < 8; q++) {
            const int id = tid + 256 * q;        // 0..2047
            const int r = id >> 4, c = id & 15;  // row, 16B-unit (16 per row)
            const uint32_t doff = SA_OFF + buf * 32768 + (c >> 3) * 16384
                                + SMEM_SWIZZLE_128B(r * 128 + (c & 7) * 16);
            cp_async16(smb + doff, Ag + (size_t)r * 2048 + ch * 256 + c * 16);
        }
        CP_COMMIT();
    };

    float acc[2][4][4];                 // [m-frag][n-frag][quad]
    #pragma unroll
    for (int mi = 0; mi < 2; mi++)
        #pragma unroll
        for (int j = 0; j < 4; j++)
            #pragma unroll
            for (int q = 0; q < 4; q++) acc[mi][j][q] = 0.f;

    // ldmatrix per-thread patterns (R10-validated)
    const int a_row = (lane & 15);
    const int a_off = (lane >> 4) * 16;
    const int b_row = ((lane >> 4) * 8) + (lane & 7);
    const int b_off = ((lane >> 3) & 1) * 16;

    copyA(0, 0);                        // groups now: [B, A0]

    #pragma unroll 1
    for (int ch = 0; ch < NCHUNKS; ch++) {
        const int buf = ch & 1;
        if (ch + 1 < NCHUNKS) {
            copyA(ch + 1, buf ^ 1);
            CP_WAIT(1);                 // A_ch (and B) complete; A_{ch+1} pending
        } else {
            CP_WAIT(0);
        }
        __syncthreads();

        const uint32_t sa = smb + SA_OFF + buf * 32768;
        #pragma unroll
        for (int ks = 0; ks < 8; ks++) {
            const uint32_t ap = sa + (ks >> 2) * 16384;
            const uint32_t koff = (ks & 3) * 32;
            uint32_t a[2][4];
            #pragma unroll
            for (int mi = 0; mi < 2; mi++)
                ldsm_x4(ap + SMEM_SWIZZLE_128B((wm + mi * 16 + a_row) * 128
                                               + koff + a_off),
                        a[mi][0], a[mi][1], a[mi][2], a[mi][3]);
            uint32_t b[2][4];
            const uint32_t bp = smb + (ch * 2 + (ks >> 2)) * 8192;
            #pragma unroll
            for (int ni = 0; ni < 2; ni++)
                ldsm_x4(bp + SMEM_SWIZZLE_128B((wn + ni * 16 + b_row) * 128
                                               + koff + b_off),
                        b[ni][0], b[ni][1], b[ni][2], b[ni][3]);
            #pragma unroll
            for (int mi = 0; mi < 2; mi++) {
                mma_tf32(acc[mi][0], a[mi][0], a[mi][1], a[mi][2], a[mi][3],
                         b[0][0], b[0][1]);
                mma_tf32(acc[mi][1], a[mi][0], a[mi][1], a[mi][2], a[mi][3],
                         b[0][2], b[0][3]);
                mma_tf32(acc[mi][2], a[mi][0], a[mi][1], a[mi][2], a[mi][3],
                         b[1][0], b[1][1]);
                mma_tf32(acc[mi][3], a[mi][0], a[mi][1], a[mi][2], a[mi][3],
                         b[1][2], b[1][3]);
            }
        }
        __syncthreads();                // A buf consumed before refill (ch+2)
    }

    // ---- epilogue: +bias, ReLU -> g_L0 ----
    {
        const int g  = lane >> 2;
        const int tq = lane & 3;
        #pragma unroll
        for (int mi = 0; mi < 2; mi++) {
            #pragma unroll
            for (int j = 0; j < 4; j++) {
                const int col = nh * 64 + wn + j * 8 + 2 * tq;
                const float bb0 = b0s[col], bb1 = b0s[col + 1];
                const size_t r0g = arow0 + wm + mi * 16 + g;
                float2 v0 = make_float2(fmaxf(acc[mi][j][0] + bb0, 0.f),
                                        fmaxf(acc[mi][j][1] + bb1, 0.f));
                float2 v1 = make_float2(fmaxf(acc[mi][j][2] + bb0, 0.f),
                                        fmaxf(acc[mi][j][3] + bb1, 0.f));
                *(float2*)&g_L0[r0g * HIDDEN + col]       = v0;
                *(float2*)&g_L0[(r0g + 8) * HIDDEN + col] = v1;
            }
        }
    }
}

// ============================================================================
// Kernel 3: final layer (unchanged math). Block 0 also resets the PDL
// counters for the next kernel_launch call (stream-ordered after gemm, so
// every execution/replay starts from zeroed counters).
// ============================================================================
__global__ __launch_bounds__(256)
void final_kernel(const float* __restrict__ history,
                  const float* __restrict__ W1,
                  const float* __restrict__ b1,
                  const int*   __restrict__ neighs1,
                  const int*   __restrict__ h_nodes,
                  float*       __restrict__ out)
{
    extern __shared__ float smf[];
    float* W1s = smf;                        // 16384 floats (64 KB)
    float* ys  = smf + 2 * HIDDEN * NCLASS;  // FB*256
    float* red = ys + FB * 2 * HIDDEN;       // FB*4*64

    const int t   = threadIdx.x;
    const int b0r = blockIdx.x * FB;

    if (blockIdx.x == 0) {              // reset handshake counters
        if (t < MT_TOTAL) g_tile_cnt[t] = 0;
        if (t == MT_TOTAL) g_bcnt = 0;
    }

    for (int i = t; i < (2 * HIDDEN * NCLASS) / 4; i += 256)
        ((float4*)W1s)[i] = ((const float4*)W1)[i];

    for (int i = t; i < FB * HIDDEN; i += 256) {
        const int r = i >> 7, c = i & 127;
        ys[r * 2 * HIDDEN + c] = g_L0[(size_t)(b0r + r) * HIDDEN + c];
    }

    {
        const int half = t >> 7;
        const int tc   = t & 127;
        #pragma unroll 1
        for (int rr = 0; rr < FB / 2; rr++) {
            const int r = rr * 2 + half;
            const int b = b0r + r;
            float s = 0.f;
            #pragma unroll
            for (int j = 0; j < K1; j++) {
                const int n1 = neighs1[b * K1 + j];
                const float no = g_L0[(size_t)(BATCH + b * K1 + j) * HIDDEN + tc];
                s += 0.5f * (no - history[(size_t)n1 * HIDDEN + tc]);
            }
            #pragma unroll
            for (int j = 0; j < NHIST; j++) {
                const int hn = h_nodes[b * NHIST + j];
                s += history[(size_t)hn * HIDDEN + tc];
            }
            ys[r * 2 * HIDDEN + HIDDEN + tc] = s * (1.f / (K1 + NHIST));
        }
    }
    __syncthreads();

    const int o  = t & 63;
    const int s4 = t >> 6;
    float acc[FB];
    #pragma unroll
    for (int r = 0; r < FB; r++) acc[r] = 0.f;
    #pragma unroll 4
    for (int kk = 0; kk < (2 * HIDDEN) / 4; kk++) {
        const int k = s4 * ((2 * HIDDEN) / 4) + kk;
        const float wv = W1s[k * NCLASS + o];
        #pragma unroll
        for (int r = 0; r < FB; r++)
            acc[r] += ys[r * 2 * HIDDEN + k] * wv;
    }
    #pragma unroll
    for (int r = 0; r < FB; r++) red[(r * 4 + s4) * 64 + o] = acc[r];
    __syncthreads();

    for (int i = t; i < FB * NCLASS; i += 256) {
        const int r = i >> 6, o2 = i & 63;
        const float v = red[(r * 4 + 0) * 64 + o2] + red[(r * 4 + 1) * 64 + o2]
                      + red[(r * 4 + 2) * 64 + o2] + red[(r * 4 + 3) * 64 + o2];
        out[(size_t)(b0r + r) * NCLASS + o2] = fmaxf(v + b1[o2], 0.f);
    }
}

// ============================================================================
// kernel_launch — graph-capturable, allocation-free.
// gemm is launched with ProgrammaticStreamSerialization (PDL) so it overlaps
// the gather tail; if the attr/launch is rejected we fall back to a plain
// launch (serial order = today's behavior, still correct).
// Input order: feats, history, W0, b0, W1, b1, nodes, neighs0, neighs1,
// neighs0_nb, h_nodes. Output: float32 [1024, 64].
// ============================================================================
extern "C" void kernel_launch(void* const* d_in, const int* in_sizes, int n_in,
                              void* d_out, int out_size)
{
    const float* feats      = (const float*)d_in[0];
    const float* history    = (const float*)d_in[1];
    const float* W0         = (const float*)d_in[2];
    const float* b0         = (const float*)d_in[3];
    const float* W1         = (const float*)d_in[4];
    const float* b1         = (const float*)d_in[5];
    const int*   nodes      = (const int*)d_in[6];
    const int*   neighs0    = (const int*)d_in[7];
    const int*   neighs1    = (const int*)d_in[8];
    const int*   neighs0_nb = (const int*)d_in[9];
    const int*   h_nodes    = (const int*)d_in[10];
    float* out = (float*)d_out;

    const int final_smem = (2 * HIDDEN * NCLASS + FB * 2 * HIDDEN + FB * 4 * 64)
                           * (int)sizeof(float);   // 72 KB
    cudaFuncSetAttribute(gemm_kernel, cudaFuncAttributeMaxDynamicSharedMemorySize,
                         GEMM_SMEM);
    cudaFuncSetAttribute(final_kernel, cudaFuncAttributeMaxDynamicSharedMemorySize,
                         final_smem);

    gather_kernel<<<GROWBLK + WBLK, 128>>>(feats, W0, nodes, neighs0, neighs1,
                                           neighs0_nb);

    // PDL launch of gemm (overlap with gather); fallback = plain serial launch
    {
        cudaLaunchConfig_t cfg = {};
        cfg.gridDim  = dim3(2 * MT_TOTAL, 1, 1);
        cfg.blockDim = dim3(256, 1, 1);
        cfg.dynamicSmemBytes = GEMM_SMEM;
        cfg.stream = 0;
        cudaLaunchAttribute attrs[1];
        attrs[0].id = cudaLaunchAttributeProgrammaticStreamSerialization;
        attrs[0].val.programmaticStreamSerializationAllowed = 1;
        cfg.attrs = attrs;
        cfg.numAttrs = 1;
        cudaError_t e = cudaLaunchKernelEx(&cfg, gemm_kernel, b0);
        if (e != cudaSuccess) {
            (void)cudaGetLastError();   // clear sticky error, go serial
            gemm_kernel<<<2 * MT_TOTAL, 256, GEMM_SMEM>>>(b0);
        }
    }

    final_kernel<<<FNBLK, 256, final_smem>>>(history, W1, b1, neighs1, h_nodes, out);
}

// round 17
// speedup vs baseline: 1.2310x; 1.2310x over previous
#include <cuda_runtime.h>
#include <cuda_bf16.h>
#include <cstdint>

// Problem constants (fixed shapes from the reference)
#define N_NODES   100000
#define NFEATS    256
#define HIDDEN    128
#define NCLASS    64
#define BATCH     1024
#define K0        25
#define K1        10
#define NHIST     5
#define ROWS_TOTAL (BATCH + BATCH * K1)   // 11264 layer0 rows
#define GROWBLK    (ROWS_TOTAL / 2)        // 5632 row blocks (2 rows each)
#define WBLK       8                       // W0-transpose blocks
#define MJOB       64                      // GEMM m-job tile
#define MJ_TOTAL   (ROWS_TOTAL / MJOB)     // 176 m-jobs per N-half
#define SLOTS      74                      // job slots per half (148 blocks)
#define KDIM       (2 * NFEATS)            // 512
#define KCH        64                      // k-chunk: A [64 rows][64 k] = 16 KB
#define NCHUNKS    (KDIM / KCH)            // 8
#define FB         4                       // roots per block in final kernel
#define FNBLK      (BATCH / FB)            // 256 blocks
// GEMM smem map: B-half 128K | A 2 x 16K chunk bufs | bias
#define SA_OFF     131072
#define B0_OFF     (SA_OFF + 2 * 16384)    // 163840
#define GEMM_SMEM  (B0_OFF + 512)          // 164352

// ---------------- device scratch ----------------
__device__ __align__(16) float g_L0[(size_t)ROWS_TOTAL * HIDDEN];
__device__ __align__(16) float g_A[(size_t)ROWS_TOTAL * KDIM];   // tf32-rounded x
__device__ __align__(16) float g_B[(size_t)HIDDEN * KDIM];       // tf32 W0^T [n][k]

#define SMEM_SWIZZLE_128B(o) ((o) ^ (((o) >> 3) & 0x70))

__device__ __forceinline__ uint32_t smem_to_u32(const void* p) {
    uint32_t a;
    asm("{ .reg .u64 t; cvta.to.shared.u64 t, %1; cvt.u32.u64 %0, t; }" : "=r"(a) : "l"(p));
    return a;
}
__device__ __forceinline__ float tf32_rna(float x) {
    uint32_t r;
    asm("cvt.rna.tf32.f32 %0, %1;" : "=r"(r) : "f"(x));
    return __uint_as_float(r);
}
__device__ __forceinline__ void cp_async16(uint32_t dst, const void* src) {
    asm volatile("cp.async.cg.shared.global [%0], [%1], 16;" :: "r"(dst), "l"(src));
}
#define CP_COMMIT()  asm volatile("cp.async.commit_group;" ::: "memory")
#define CP_WAIT(n)   asm volatile("cp.async.wait_group %0;" :: "n"(n) : "memory")

__device__ __forceinline__ void ldsm_x4(uint32_t addr, uint32_t& r0, uint32_t& r1,
                                        uint32_t& r2, uint32_t& r3) {
    asm volatile("ldmatrix.sync.aligned.m8n8.x4.shared.b16 {%0,%1,%2,%3}, [%4];"
                 : "=r"(r0), "=r"(r1), "=r"(r2), "=r"(r3) : "r"(addr));
}
__device__ __forceinline__ void mma_tf32(float* d, uint32_t a0, uint32_t a1,
                                         uint32_t a2, uint32_t a3,
                                         uint32_t b0, uint32_t b1) {
    asm volatile(
        "mma.sync.aligned.m16n8k8.row.col.f32.tf32.tf32.f32 "
        "{%0,%1,%2,%3}, {%4,%5,%6,%7}, {%8,%9}, {%0,%1,%2,%3};"
        : "+f"(d[0]), "+f"(d[1]), "+f"(d[2]), "+f"(d[3])
        : "r"(a0), "r"(a1), "r"(a2), "r"(a3), "r"(b0), "r"(b1));
}

// ============================================================================
// Kernel 1: gather + mean -> tf32-rounded fp32 scratch. (R14-identical; at
// the LTS-throughput floor ~35 us. PDL removed.)
// ============================================================================
__global__ __launch_bounds__(128)
void gather_kernel(const float* __restrict__ feats,
                   const float* __restrict__ W0,
                   const int*   __restrict__ nodes,
                   const int*   __restrict__ neighs0,
                   const int*   __restrict__ neighs1,
                   const int*   __restrict__ neighs0_nb)
{
    const int t = threadIdx.x;

    if (blockIdx.x >= GROWBLK) {        // ---- W0 transpose (tf32), full 64K ----
        const int b = blockIdx.x - GROWBLK;
        #pragma unroll 4
        for (int j = 0; j < 64; j++) {
            const int idx = b * 8192 + j * 128 + t;   // idx = k*128 + n
            const int k = idx >> 7, n = idx & 127;
            g_B[(size_t)n * KDIM + k] = tf32_rna(W0[idx]);
        }
        return;
    }

    const int half = t >> 6;
    const int tc   = t & 63;
    const int row  = blockIdx.x * 2 + half;
    const float4* f4 = (const float4*)feats;

    int self;
    const int* nb;
    if (row < BATCH) {
        self = nodes[row];
        nb   = neighs0 + row * K0;
    } else {
        const int j = row - BATCH;
        self = neighs1[j];
        nb   = neighs0_nb + j * K0;
    }
    const float4 sv = f4[(size_t)self * (NFEATS / 4) + tc];
    float s0 = 0.f, s1 = 0.f, s2 = 0.f, s3 = 0.f;
    #pragma unroll
    for (int k = 0; k < K0; k++) {
        const float4 v = f4[(size_t)nb[k] * (NFEATS / 4) + tc];
        s0 += v.x; s1 += v.y; s2 += v.z; s3 += v.w;
    }
    const float inv = 1.f / K0;

    float4* A4 = (float4*)(g_A + (size_t)row * KDIM);
    A4[tc] = make_float4(tf32_rna(sv.x), tf32_rna(sv.y),
                         tf32_rna(sv.z), tf32_rna(sv.w));
    A4[64 + tc] = make_float4(tf32_rna(s0 * inv), tf32_rna(s1 * inv),
                              tf32_rna(s2 * inv), tf32_rna(s3 * inv));
}

// ============================================================================
// Kernel 2: BALANCED PERSISTENT TF32 GEMM.
// grid 148 x 256 thr. bid: nh = bid&1 (N-half of 64 cols), slot = bid>>1.
// - Stage B-half [64 n][512 k] (128 KB) ONCE (16 k-planes x 8 KB).
// - Jobs = M64 tiles, slot handles mj = slot, slot+74, slot+148 (<176):
//   max 3 jobs = 6144 mma vs R14's 2-wave max 8192 -> ~25% makespan cut.
// - Per job: A [64 rows][512 k] streamed in 8 chunks of 16 KB, double-buffered.
// Warp layout: 8 positions of 16 rows x 32 cols  (wm=(w&3)*16, wn=(w>>2)*32);
// per k-step: 1 A-ldsm + 2 B-ldsm + 4 mma; 4 accumulator chains per warp.
// Fragment maps are the R10-validated ones.
// ============================================================================
__global__ __launch_bounds__(256)
void gemm_kernel(const float* __restrict__ b0)
{
    extern __shared__ __align__(1024) char sm[];
    float* b0s = (float*)(sm + B0_OFF);
    const uint32_t smb = smem_to_u32(sm);
    const int tid  = threadIdx.x;
    const int lane = tid & 31;
    const int w    = tid >> 5;
    const int wm   = (w & 3) * 16;      // 4 m-strips of 16 rows
    const int wn   = (w >> 2) * 32;     // 2 n-strips of 32 cols (within half)
    const int nh   = blockIdx.x & 1;
    const int slot = blockIdx.x >> 1;   // 0..73

    for (int i = tid; i < HIDDEN; i += 256) b0s[i] = b0[i];

    // ---- stage B-half once: 8192 x 16B units, 32 per thread ----
    {
        const char* Bh = (const char*)(g_B + (size_t)(nh * 64) * KDIM);
        #pragma unroll
        for (int q = 0; q < 32; q++) {
            const int id = tid + 256 * q;        // 0..8191
            const int r = id >> 7, c = id & 127; // n-row, 16B-unit
            const uint32_t doff = (c >> 3) * 8192
                                + SMEM_SWIZZLE_128B(r * 128 + (c & 7) * 16);
            cp_async16(smb + doff, Bh + (size_t)r * 2048 + c * 16);
        }
        CP_COMMIT();                             // group: B
    }

    // ldmatrix per-thread patterns (R10-validated)
    const int a_row = (lane & 15);
    const int a_off = (lane >> 4) * 16;
    const int b_row = ((lane >> 4) * 8) + (lane & 7);
    const int b_off = ((lane >> 3) & 1) * 16;

    for (int mj = slot; mj < MJ_TOTAL; mj += SLOTS) {
        const size_t arow0 = (size_t)mj * MJOB;
        const char* Ag = (const char*)(g_A + arow0 * KDIM);

        // A chunk copy: [64 rows][64 k] = 1024 x 16B units, 4 per thread
        auto copyA = [&](int ch, int buf) {
            #pragma unroll
            for (int q = 0; q < 4; q++) {
                const int id = tid + 256 * q;    // 0..1023
                const int r = id >> 4, c = id & 15;
                const uint32_t doff = SA_OFF + buf * 16384 + (c >> 3) * 8192
                                    + SMEM_SWIZZLE_128B(r * 128 + (c & 7) * 16);
                cp_async16(smb + doff, Ag + (size_t)r * 2048 + ch * 256 + c * 16);
            }
            CP_COMMIT();
        };

        float acc[4][4];                 // 4 n-frags of m16n8
        #pragma unroll
        for (int j = 0; j < 4; j++)
            #pragma unroll
            for (int q = 0; q < 4; q++) acc[j][q] = 0.f;

        copyA(0, 0);

        #pragma unroll 1
        for (int ch = 0; ch < NCHUNKS; ch++) {
            const int buf = ch & 1;
            if (ch + 1 < NCHUNKS) {
                copyA(ch + 1, buf ^ 1);
                CP_WAIT(1);             // A_ch (and B/A_{ch-1}) complete
            } else {
                CP_WAIT(0);
            }
            __syncthreads();

            const uint32_t sa = smb + SA_OFF + buf * 16384;
            #pragma unroll
            for (int ks = 0; ks < 8; ks++) {
                const uint32_t koff = (ks & 3) * 32;
                uint32_t a0, a1, a2, a3;
                ldsm_x4(sa + (ks >> 2) * 8192
                            + SMEM_SWIZZLE_128B((wm + a_row) * 128 + koff + a_off),
                        a0, a1, a2, a3);
                const uint32_t bp = smb + (ch * 2 + (ks >> 2)) * 8192;
                uint32_t p0, p1, p2, p3, q0, q1, q2, q3;
                ldsm_x4(bp + SMEM_SWIZZLE_128B((wn + b_row) * 128 + koff + b_off),
                        p0, p1, p2, p3);
                ldsm_x4(bp + SMEM_SWIZZLE_128B((wn + 16 + b_row) * 128 + koff + b_off),
                        q0, q1, q2, q3);
                mma_tf32(acc[0], a0, a1, a2, a3, p0, p1);
                mma_tf32(acc[1], a0, a1, a2, a3, p2, p3);
                mma_tf32(acc[2], a0, a1, a2, a3, q0, q1);
                mma_tf32(acc[3], a0, a1, a2, a3, q2, q3);
            }
            __syncthreads();            // buf consumed before refill (ch+2)
        }

        // ---- epilogue: +bias, ReLU -> g_L0 ----
        {
            const int g  = lane >> 2;
            const int tq = lane & 3;
            #pragma unroll
            for (int j = 0; j < 4; j++) {
                const int col = nh * 64 + wn + j * 8 + 2 * tq;
                const float bb0 = b0s[col], bb1 = b0s[col + 1];
                const size_t r0g = arow0 + wm + g;
                float2 v0 = make_float2(fmaxf(acc[j][0] + bb0, 0.f),
                                        fmaxf(acc[j][1] + bb1, 0.f));
                float2 v1 = make_float2(fmaxf(acc[j][2] + bb0, 0.f),
                                        fmaxf(acc[j][3] + bb1, 0.f));
                *(float2*)&g_L0[r0g * HIDDEN + col]       = v0;
                *(float2*)&g_L0[(r0g + 8) * HIDDEN + col] = v1;
            }
        }
    }
}

// ============================================================================
// Kernel 3: final layer. FB=4 roots/block, grid 256, 256 thr, W1 staged in
// smem, 4-way split-K. (R14-identical)
// ============================================================================
__global__ __launch_bounds__(256)
void final_kernel(const float* __restrict__ history,
                  const float* __restrict__ W1,
                  const float* __restrict__ b1,
                  const int*   __restrict__ neighs1,
                  const int*   __restrict__ h_nodes,
                  float*       __restrict__ out)
{
    extern __shared__ float smf[];
    float* W1s = smf;                        // 16384 floats (64 KB)
    float* ys  = smf + 2 * HIDDEN * NCLASS;  // FB*256
    float* red = ys + FB * 2 * HIDDEN;       // FB*4*64

    const int t   = threadIdx.x;
    const int b0r = blockIdx.x * FB;

    for (int i = t; i < (2 * HIDDEN * NCLASS) / 4; i += 256)
        ((float4*)W1s)[i] = ((const float4*)W1)[i];

    for (int i = t; i < FB * HIDDEN; i += 256) {
        const int r = i >> 7, c = i & 127;
        ys[r * 2 * HIDDEN + c] = g_L0[(size_t)(b0r + r) * HIDDEN + c];
    }

    {
        const int half = t >> 7;
        const int tc   = t & 127;
        #pragma unroll 1
        for (int rr = 0; rr < FB / 2; rr++) {
            const int r = rr * 2 + half;
            const int b = b0r + r;
            float s = 0.f;
            #pragma unroll
            for (int j = 0; j < K1; j++) {
                const int n1 = neighs1[b * K1 + j];
                const float no = g_L0[(size_t)(BATCH + b * K1 + j) * HIDDEN + tc];
                s += 0.5f * (no - history[(size_t)n1 * HIDDEN + tc]);
            }
            #pragma unroll
            for (int j = 0; j < NHIST; j++) {
                const int hn = h_nodes[b * NHIST + j];
                s += history[(size_t)hn * HIDDEN + tc];
            }
            ys[r * 2 * HIDDEN + HIDDEN + tc] = s * (1.f / (K1 + NHIST));
        }
    }
    __syncthreads();

    const int o  = t & 63;
    const int s4 = t >> 6;
    float acc[FB];
    #pragma unroll
    for (int r = 0; r < FB; r++) acc[r] = 0.f;
    #pragma unroll 4
    for (int kk = 0; kk < (2 * HIDDEN) / 4; kk++) {
        const int k = s4 * ((2 * HIDDEN) / 4) + kk;
        const float wv = W1s[k * NCLASS + o];
        #pragma unroll
        for (int r = 0; r < FB; r++)
            acc[r] += ys[r * 2 * HIDDEN + k] * wv;
    }
    #pragma unroll
    for (int r = 0; r < FB; r++) red[(r * 4 + s4) * 64 + o] = acc[r];
    __syncthreads();

    for (int i = t; i < FB * NCLASS; i += 256) {
        const int r = i >> 6, o2 = i & 63;
        const float v = red[(r * 4 + 0) * 64 + o2] + red[(r * 4 + 1) * 64 + o2]
                      + red[(r * 4 + 2) * 64 + o2] + red[(r * 4 + 3) * 64 + o2];
        out[(size_t)(b0r + r) * NCLASS + o2] = fmaxf(v + b1[o2], 0.f);
    }
}

// ============================================================================
// kernel_launch — graph-capturable, allocation-free. Serial launches (PDL
// reverted: overlap measurably regressed in R15).
// Input order: feats, history, W0, b0, W1, b1, nodes, neighs0, neighs1,
// neighs0_nb, h_nodes. Output: float32 [1024, 64].
// ============================================================================
extern "C" void kernel_launch(void* const* d_in, const int* in_sizes, int n_in,
                              void* d_out, int out_size)
{
    const float* feats      = (const float*)d_in[0];
    const float* history    = (const float*)d_in[1];
    const float* W0         = (const float*)d_in[2];
    const float* b0         = (const float*)d_in[3];
    const float* W1         = (const float*)d_in[4];
    const float* b1         = (const float*)d_in[5];
    const int*   nodes      = (const int*)d_in[6];
    const int*   neighs0    = (const int*)d_in[7];
    const int*   neighs1    = (const int*)d_in[8];
    const int*   neighs0_nb = (const int*)d_in[9];
    const int*   h_nodes    = (const int*)d_in[10];
    float* out = (float*)d_out;

    const int final_smem = (2 * HIDDEN * NCLASS + FB * 2 * HIDDEN + FB * 4 * 64)
                           * (int)sizeof(float);   // 72 KB
    cudaFuncSetAttribute(gemm_kernel, cudaFuncAttributeMaxDynamicSharedMemorySize,
                         GEMM_SMEM);
    cudaFuncSetAttribute(final_kernel, cudaFuncAttributeMaxDynamicSharedMemorySize,
                         final_smem);

    gather_kernel<<<GROWBLK + WBLK, 128>>>(feats, W0, nodes, neighs0, neighs1,
                                           neighs0_nb);
    gemm_kernel<<<2 * SLOTS, 256, GEMM_SMEM>>>(b0);
    final_kernel<<<FNBLK, 256, final_smem>>>(history, W1, b1, neighs1, h_nodes, out);
}